// round 12
// baseline (speedup 1.0000x reference)
#include <cuda_runtime.h>
#include <cuda_bf16.h>

// Problem constants
#define NB     50      // buckets
#define HID    32
#define HALF   16
#define GRID   608     // 152 SMs * 4 resident blocks (persistent grid-stride)
#define BLOCK  256

// Precomputed tables (device globals — no allocation allowed).
// g_v layout: per bucket id, 9 float4 slots at stride 9:
//   slots 0..7 = v[id][4q..4q+3]  (v = W2 @ Wh[id], folded layer-2)
//   slot  8.x  = c[id] = b2 . Wh[id] + bh[id]   (folded bias)
// Bank-group of slot q is (id+q) mod 8; addressing linear (imm offsets).
__device__ float4 g_v[NB * 9];
// W1/b1 as SoA float4 chunks: A=W1[0][:], B=W1[1][:], C=b1[:]
__device__ float4 g_A[HID / 4];
__device__ float4 g_B[HID / 4];
__device__ float4 g_C[HID / 4];

// ---------------------------------------------------------------------------
// Kernel 1: fold W2 (and b2,bh) into per-bucket heads + repack W1.
// ---------------------------------------------------------------------------
__global__ void lw_precompute(const float* __restrict__ W1,
                              const float* __restrict__ b1,
                              const float* __restrict__ W2,
                              const float* __restrict__ b2,
                              const float* __restrict__ Wh,
                              const float* __restrict__ bh) {
    int t = blockIdx.x * blockDim.x + threadIdx.x;
    if (t < NB * HID) {
        int id = t >> 5;
        int j  = t & 31;
        float acc = 0.f;
#pragma unroll
        for (int m = 0; m < HALF; m++)
            acc = fmaf(W2[j * HALF + m], Wh[id * HALF + m], acc);
        reinterpret_cast<float*>(g_v)[id * 36 + j] = acc;
    } else if (t < NB * HID + NB) {
        int id = t - NB * HID;
        float acc = bh[id];
#pragma unroll
        for (int m = 0; m < HALF; m++)
            acc = fmaf(b2[m], Wh[id * HALF + m], acc);
        reinterpret_cast<float*>(g_v)[id * 36 + 32] = acc;
    } else if (t < NB * HID + NB + HID) {
        int j = t - (NB * HID + NB);
        reinterpret_cast<float*>(g_A)[j] = W1[j];
        reinterpret_cast<float*>(g_B)[j] = W1[HID + j];
        reinterpret_cast<float*>(g_C)[j] = b1[j];
    }
}

// Per-row inner step for one q-group of 4 hidden units.
__device__ __forceinline__ void row_step(const float4 A, const float4 Bw,
                                         const float4 C, const float4 u,
                                         const float xa, const float xb,
                                         float& a, float& b) {
    float h;
    h = fmaxf(fmaf(xa, A.x, fmaf(xb, Bw.x, C.x)), 0.f); a = fmaf(h, u.x, a);
    h = fmaxf(fmaf(xa, A.y, fmaf(xb, Bw.y, C.y)), 0.f); b = fmaf(h, u.y, b);
    h = fmaxf(fmaf(xa, A.z, fmaf(xb, Bw.z, C.z)), 0.f); a = fmaf(h, u.z, a);
    h = fmaxf(fmaf(xa, A.w, fmaf(xb, Bw.w, C.w)), 0.f); b = fmaf(h, u.w, b);
}

// ---------------------------------------------------------------------------
// Kernel 2: main. FOUR consecutive rows per thread (2x float4 x, int4
// buckets, float4 out). 4 resident blocks/SM (regs capped at 64).
// out[r] = sum_j relu(x0*A_j + x1*B_j + C_j) * v[id][j] + c[id]
// ---------------------------------------------------------------------------
__global__ __launch_bounds__(BLOCK, 4)
void lw_main(const float4* __restrict__ x4,
             const int4*   __restrict__ bk4,
             float4*       __restrict__ out4,
             int nquads,
             const float*  __restrict__ x_s,
             const int*    __restrict__ bk_s,
             float*        __restrict__ out_s,
             int B) {
    __shared__ float4 s_v[NB * 9];
    __shared__ float4 s_A[HID / 4];
    __shared__ float4 s_B[HID / 4];
    __shared__ float4 s_C[HID / 4];

    for (int i = threadIdx.x; i < NB * 9; i += BLOCK) s_v[i] = g_v[i];
    if (threadIdx.x < HID / 4) {
        s_A[threadIdx.x] = g_A[threadIdx.x];
        s_B[threadIdx.x] = g_B[threadIdx.x];
        s_C[threadIdx.x] = g_C[threadIdx.x];
    }
    __syncthreads();

    const int T = gridDim.x * blockDim.x;
    const int tid = blockIdx.x * blockDim.x + threadIdx.x;

    for (int p = tid; p < nquads; p += T) {
        const int4   ids = bk4[p];
        const float4 xA  = x4[2 * p + 0];   // rows 0,1: (x0a,x0b,x1a,x1b)
        const float4 xB  = x4[2 * p + 1];   // rows 2,3
        const float4* v0 = s_v + min((unsigned)ids.x, NB - 1u) * 9;
        const float4* v1 = s_v + min((unsigned)ids.y, NB - 1u) * 9;
        const float4* v2 = s_v + min((unsigned)ids.z, NB - 1u) * 9;
        const float4* v3 = s_v + min((unsigned)ids.w, NB - 1u) * 9;

        float a0 = v0[8].x, b0 = 0.f;   // c[id] folded into acc init
        float a1 = v1[8].x, b1r = 0.f;
        float a2 = v2[8].x, b2r = 0.f;
        float a3 = v3[8].x, b3r = 0.f;

#pragma unroll
        for (int q = 0; q < 8; q++) {
            const float4 A  = s_A[q];
            const float4 Bw = s_B[q];
            const float4 C  = s_C[q];
            row_step(A, Bw, C, v0[q], xA.x, xA.y, a0, b0);
            row_step(A, Bw, C, v1[q], xA.z, xA.w, a1, b1r);
            row_step(A, Bw, C, v2[q], xB.x, xB.y, a2, b2r);
            row_step(A, Bw, C, v3[q], xB.z, xB.w, a3, b3r);
        }
        out4[p] = make_float4(a0 + b0, a1 + b1r, a2 + b2r, a3 + b3r);
    }

    // Tail: up to 3 scalar rows.
    const int rem = B & 3;
    if (tid < rem) {
        const int r = (nquads << 2) + tid;
        const unsigned id = min((unsigned)bk_s[r], NB - 1u);
        const float4* v = s_v + id * 9;
        const float xa = x_s[2 * r], xb = x_s[2 * r + 1];
        float a = v[8].x, b = 0.f;
#pragma unroll
        for (int q = 0; q < 8; q++)
            row_step(s_A[q], s_B[q], s_C[q], v[q], xa, xb, a, b);
        out_s[r] = a + b;
    }
}

// ---------------------------------------------------------------------------
// Inputs (metadata order): x[B,2] f32, buckets[B] i32, W1[2,32], b1[32],
//                          W2[32,16], b2[16], Wh[50,16], bh[50]
// Output: float[B]
// ---------------------------------------------------------------------------
extern "C" void kernel_launch(void* const* d_in, const int* in_sizes, int n_in,
                              void* d_out, int out_size) {
    const float* x  = (const float*)d_in[0];
    const int*   bk = (const int*)d_in[1];
    const float* W1 = (const float*)d_in[2];
    const float* b1 = (const float*)d_in[3];
    const float* W2 = (const float*)d_in[4];
    const float* b2 = (const float*)d_in[5];
    const float* Wh = (const float*)d_in[6];
    const float* bh = (const float*)d_in[7];
    float* out = (float*)d_out;

    const int B = in_sizes[1];
    const int nquads = B >> 2;

    lw_precompute<<<14, 128>>>(W1, b1, W2, b2, Wh, bh);
    lw_main<<<GRID, BLOCK>>>((const float4*)x, (const int4*)bk, (float4*)out,
                             nquads, x, bk, out, B);
}

// round 13
// speedup vs baseline: 1.8544x; 1.8544x over previous
#include <cuda_runtime.h>
#include <cuda_bf16.h>

// Problem constants
#define NB     50      // buckets
#define HID    32
#define HALF   16
#define GRID   304     // 152 SMs * 2 resident blocks (persistent grid-stride)
#define BLOCK  256

typedef unsigned long long ull;

// Precomputed tables (device globals — no allocation allowed).
// g_v layout: per bucket id, 9 float4 slots at stride 9:
//   slots 0..7 = v[id][4q..4q+3]  (v = W2 @ Wh[id], folded layer-2)
//   slot  8.x  = c[id] = b2 . Wh[id] + bh[id]   (folded bias)
// Bank-group of slot q is (id+q) mod 8; addressing linear (imm offsets).
__device__ float4 g_v[NB * 9];
// W1/b1 packed as f32 pairs: A = W1[0][:], B = W1[1][:], C = b1[:]
__device__ float2 g_A[HID / 2];
__device__ float2 g_B[HID / 2];
__device__ float2 g_C[HID / 2];

// ---------------------------------------------------------------------------
// Packed f32x2 helpers (Blackwell FFMA2 — only reachable via explicit PTX).
// ---------------------------------------------------------------------------
__device__ __forceinline__ ull pack2(float lo, float hi) {
    ull r;
    asm("mov.b64 %0, {%1, %2};" : "=l"(r) : "f"(lo), "f"(hi));
    return r;
}
__device__ __forceinline__ ull fma2(ull a, ull b, ull c) {
    ull d;
    asm("fma.rn.f32x2 %0, %1, %2, %3;" : "=l"(d) : "l"(a), "l"(b), "l"(c));
    return d;
}
// relu on a packed pair: scalar FMNMX on the two halves (alu pipe has slack);
// pack/unpack movs are register-pair aliases, normally elided by ptxas.
__device__ __forceinline__ ull relu2(ull t) {
    float lo, hi;
    asm("mov.b64 {%0, %1}, %2;" : "=f"(lo), "=f"(hi) : "l"(t));
    return pack2(fmaxf(lo, 0.f), fmaxf(hi, 0.f));
}
__device__ __forceinline__ float hsum2(ull t) {
    float lo, hi;
    asm("mov.b64 {%0, %1}, %2;" : "=f"(lo), "=f"(hi) : "l"(t));
    return lo + hi;
}

// ---------------------------------------------------------------------------
// Kernel 1: fold W2 (and b2,bh) into per-bucket heads + repack W1.
// ---------------------------------------------------------------------------
__global__ void lw_precompute(const float* __restrict__ W1,
                              const float* __restrict__ b1,
                              const float* __restrict__ W2,
                              const float* __restrict__ b2,
                              const float* __restrict__ Wh,
                              const float* __restrict__ bh) {
    int t = blockIdx.x * blockDim.x + threadIdx.x;
    if (t < NB * HID) {
        int id = t >> 5;
        int j  = t & 31;
        float acc = 0.f;
#pragma unroll
        for (int m = 0; m < HALF; m++)
            acc = fmaf(W2[j * HALF + m], Wh[id * HALF + m], acc);
        reinterpret_cast<float*>(g_v)[id * 36 + j] = acc;
    } else if (t < NB * HID + NB) {
        int id = t - NB * HID;
        float acc = bh[id];
#pragma unroll
        for (int m = 0; m < HALF; m++)
            acc = fmaf(b2[m], Wh[id * HALF + m], acc);
        reinterpret_cast<float*>(g_v)[id * 36 + 32] = acc;
    } else if (t < NB * HID + NB + HID) {
        int j = t - (NB * HID + NB);
        reinterpret_cast<float*>(g_A)[j] = W1[j];
        reinterpret_cast<float*>(g_B)[j] = W1[HID + j];
        reinterpret_cast<float*>(g_C)[j] = b1[j];
    }
}

// ---------------------------------------------------------------------------
// Kernel 2: main. Two consecutive rows per thread (float4 x, int2 buckets,
// float2 out), packed f32x2 math: per j-pair t = xa*A + (xb*B + C),
// h = relu(t), acc += h * v.  out[r] = hsum(acc) (+ c folded into acc init).
// ---------------------------------------------------------------------------
__global__ __launch_bounds__(BLOCK, 2)
void lw_main(const float4* __restrict__ x2,
             const int2*   __restrict__ bk2,
             float2*       __restrict__ out2,
             int npairs,
             const float*  __restrict__ x_s,
             const int*    __restrict__ bk_s,
             float*        __restrict__ out_s,
             int B) {
    __shared__ float4 s_v[NB * 9];

    for (int i = threadIdx.x; i < NB * 9; i += BLOCK) s_v[i] = g_v[i];
    __syncthreads();

    // Hoist W1 into registers as packed pairs (96 regs, broadcast LDG, cached).
    ull rA[HID / 2], rB[HID / 2], rC[HID / 2];
#pragma unroll
    for (int j = 0; j < HID / 2; j++) {
        float2 a = g_A[j], b = g_B[j], c = g_C[j];
        rA[j] = pack2(a.x, a.y);
        rB[j] = pack2(b.x, b.y);
        rC[j] = pack2(c.x, c.y);
    }

    const int T = gridDim.x * blockDim.x;
    const int tid = blockIdx.x * blockDim.x + threadIdx.x;

    for (int p = tid; p < npairs; p += T) {
        const int2   ids = bk2[p];
        const float4 xp  = x2[p];
        const float4* v0 = s_v + min((unsigned)ids.x, NB - 1u) * 9;
        const float4* v1 = s_v + min((unsigned)ids.y, NB - 1u) * 9;

        const ull xa0 = pack2(xp.x, xp.x), xb0 = pack2(xp.y, xp.y);
        const ull xa1 = pack2(xp.z, xp.z), xb1 = pack2(xp.w, xp.w);

        ull acc0 = pack2(v0[8].x, 0.f);   // c[id] folded into acc init
        ull acc1 = pack2(v1[8].x, 0.f);

#pragma unroll
        for (int q = 0; q < 8; q++) {
            const float4 u0 = v0[q];
            const float4 u1 = v1[q];
            ull t;
            t = fma2(xa0, rA[2 * q + 0], fma2(xb0, rB[2 * q + 0], rC[2 * q + 0]));
            acc0 = fma2(relu2(t), pack2(u0.x, u0.y), acc0);
            t = fma2(xa0, rA[2 * q + 1], fma2(xb0, rB[2 * q + 1], rC[2 * q + 1]));
            acc0 = fma2(relu2(t), pack2(u0.z, u0.w), acc0);
            t = fma2(xa1, rA[2 * q + 0], fma2(xb1, rB[2 * q + 0], rC[2 * q + 0]));
            acc1 = fma2(relu2(t), pack2(u1.x, u1.y), acc1);
            t = fma2(xa1, rA[2 * q + 1], fma2(xb1, rB[2 * q + 1], rC[2 * q + 1]));
            acc1 = fma2(relu2(t), pack2(u1.z, u1.w), acc1);
        }
        out2[p] = make_float2(hsum2(acc0), hsum2(acc1));
    }

    // Odd-B tail: one scalar row handled by a single thread.
    if ((B & 1) && tid == 0) {
        const int r = B - 1;
        const unsigned id = min((unsigned)bk_s[r], NB - 1u);
        const float4* v = s_v + id * 9;
        const ull xa = pack2(x_s[2 * r], x_s[2 * r]);
        const ull xb = pack2(x_s[2 * r + 1], x_s[2 * r + 1]);
        ull acc = pack2(v[8].x, 0.f);
#pragma unroll
        for (int q = 0; q < 8; q++) {
            const float4 u = v[q];
            ull t;
            t = fma2(xa, rA[2 * q + 0], fma2(xb, rB[2 * q + 0], rC[2 * q + 0]));
            acc = fma2(relu2(t), pack2(u.x, u.y), acc);
            t = fma2(xa, rA[2 * q + 1], fma2(xb, rB[2 * q + 1], rC[2 * q + 1]));
            acc = fma2(relu2(t), pack2(u.z, u.w), acc);
        }
        out_s[r] = hsum2(acc);
    }
}

// ---------------------------------------------------------------------------
// Inputs (metadata order): x[B,2] f32, buckets[B] i32, W1[2,32], b1[32],
//                          W2[32,16], b2[16], Wh[50,16], bh[50]
// Output: float[B]
// ---------------------------------------------------------------------------
extern "C" void kernel_launch(void* const* d_in, const int* in_sizes, int n_in,
                              void* d_out, int out_size) {
    const float* x  = (const float*)d_in[0];
    const int*   bk = (const int*)d_in[1];
    const float* W1 = (const float*)d_in[2];
    const float* b1 = (const float*)d_in[3];
    const float* W2 = (const float*)d_in[4];
    const float* b2 = (const float*)d_in[5];
    const float* Wh = (const float*)d_in[6];
    const float* bh = (const float*)d_in[7];
    float* out = (float*)d_out;

    const int B = in_sizes[1];
    const int npairs = B >> 1;

    lw_precompute<<<14, 128>>>(W1, b1, W2, b2, Wh, bh);
    lw_main<<<GRID, BLOCK>>>((const float4*)x, (const int2*)bk, (float2*)out,
                             npairs, x, bk, out, B);
}

// round 14
// speedup vs baseline: 2.1554x; 1.1623x over previous
#include <cuda_runtime.h>
#include <cuda_fp16.h>
#include <cuda_bf16.h>

// Problem constants
#define NB     50      // buckets
#define HID    32
#define HALF   16
#define GRID   304     // 152 SMs * 2 resident blocks (persistent grid-stride)
#define BLOCK  256

typedef unsigned long long ull;

// Precomputed tables (device globals — no allocation allowed).
// g_vh: per bucket id, 9 uint2 slots (stride 9; slots 0..7 hold v[id][4q..4q+3]
// as 4 halves, slot 8 = pad). Bank-pair group of slot q is (9*id+q) mod 16 ->
// good spread for random ids, linear addressing (imm offsets).
__device__ uint2  g_vh[NB * 9];
__device__ float  g_c[NB];         // c[id] = b2 . Wh[id] + bh[id]  (fp32)
// W1/b1 packed as f32 pairs: A = W1[0][:], B = W1[1][:], C = b1[:]
__device__ float2 g_A[HID / 2];
__device__ float2 g_B[HID / 2];
__device__ float2 g_C[HID / 2];

// ---------------------------------------------------------------------------
// Packed f32x2 helpers (Blackwell FFMA2 — only reachable via explicit PTX).
// ---------------------------------------------------------------------------
__device__ __forceinline__ ull pack2(float lo, float hi) {
    ull r;
    asm("mov.b64 %0, {%1, %2};" : "=l"(r) : "f"(lo), "f"(hi));
    return r;
}
__device__ __forceinline__ ull fma2(ull a, ull b, ull c) {
    ull d;
    asm("fma.rn.f32x2 %0, %1, %2, %3;" : "=l"(d) : "l"(a), "l"(b), "l"(c));
    return d;
}
__device__ __forceinline__ ull relu2(ull t) {
    float lo, hi;
    asm("mov.b64 {%0, %1}, %2;" : "=f"(lo), "=f"(hi) : "l"(t));
    return pack2(fmaxf(lo, 0.f), fmaxf(hi, 0.f));
}
__device__ __forceinline__ float hsum2(ull t) {
    float lo, hi;
    asm("mov.b64 {%0, %1}, %2;" : "=f"(lo), "=f"(hi) : "l"(t));
    return lo + hi;
}
// uint32 holding half2 -> packed f32x2 (2x F2F.F32.F16 with H0/H1 select)
__device__ __forceinline__ ull h2_to_f2(unsigned u) {
    __half2 h = *reinterpret_cast<__half2*>(&u);
    float2 f = __half22float2(h);
    return pack2(f.x, f.y);
}

// ---------------------------------------------------------------------------
// Kernel 1: fold W2 (and b2,bh) into per-bucket heads + repack W1.
// ---------------------------------------------------------------------------
__global__ void lw_precompute(const float* __restrict__ W1,
                              const float* __restrict__ b1,
                              const float* __restrict__ W2,
                              const float* __restrict__ b2,
                              const float* __restrict__ Wh,
                              const float* __restrict__ bh) {
    int t = blockIdx.x * blockDim.x + threadIdx.x;
    if (t < NB * HID) {
        int id = t >> 5;
        int j  = t & 31;
        float acc = 0.f;
#pragma unroll
        for (int m = 0; m < HALF; m++)
            acc = fmaf(W2[j * HALF + m], Wh[id * HALF + m], acc);
        // half storage: id-stride 36 halves, slot q=(j>>2), lane j&3
        reinterpret_cast<__half*>(g_vh)[id * 36 + j] = __float2half_rn(acc);
    } else if (t < NB * HID + NB) {
        int id = t - NB * HID;
        float acc = bh[id];
#pragma unroll
        for (int m = 0; m < HALF; m++)
            acc = fmaf(b2[m], Wh[id * HALF + m], acc);
        g_c[id] = acc;
    } else if (t < NB * HID + NB + HID) {
        int j = t - (NB * HID + NB);
        reinterpret_cast<float*>(g_A)[j] = W1[j];
        reinterpret_cast<float*>(g_B)[j] = W1[HID + j];
        reinterpret_cast<float*>(g_C)[j] = b1[j];
    }
}

// ---------------------------------------------------------------------------
// Kernel 2: main. Two consecutive rows per thread (float4 x, int2 buckets,
// float2 out), packed f32x2 math, fp16 v-table gather (LDS.64), fp32 bias,
// software prefetch of next iteration's x/buckets.
// ---------------------------------------------------------------------------
__global__ __launch_bounds__(BLOCK, 2)
void lw_main(const float4* __restrict__ x2,
             const int2*   __restrict__ bk2,
             float2*       __restrict__ out2,
             int npairs,
             const float*  __restrict__ x_s,
             const int*    __restrict__ bk_s,
             float*        __restrict__ out_s,
             int B) {
    __shared__ uint2 s_vh[NB * 9];
    __shared__ float s_c[NB];

    for (int i = threadIdx.x; i < NB * 9; i += BLOCK) s_vh[i] = g_vh[i];
    if (threadIdx.x < NB) s_c[threadIdx.x] = g_c[threadIdx.x];
    __syncthreads();

    // Hoist W1 into registers as packed pairs (96 regs, broadcast LDG, cached).
    ull rA[HID / 2], rB[HID / 2], rC[HID / 2];
#pragma unroll
    for (int j = 0; j < HID / 2; j++) {
        float2 a = g_A[j], b = g_B[j], c = g_C[j];
        rA[j] = pack2(a.x, a.y);
        rB[j] = pack2(b.x, b.y);
        rC[j] = pack2(c.x, c.y);
    }

    const int T = gridDim.x * blockDim.x;
    const int tid = blockIdx.x * blockDim.x + threadIdx.x;

    if (tid < npairs) {
        int2   ids = bk2[tid];
        float4 xp  = x2[tid];
        for (int p = tid; p < npairs; ) {
            const int pn = p + T;
            int2   ids_n;
            float4 xp_n;
            if (pn < npairs) {           // prefetch next iteration's inputs
                ids_n = bk2[pn];
                xp_n  = x2[pn];
            }

            const unsigned i0 = min((unsigned)ids.x, NB - 1u);
            const unsigned i1 = min((unsigned)ids.y, NB - 1u);
            const uint2* v0 = s_vh + i0 * 9;
            const uint2* v1 = s_vh + i1 * 9;

            const ull xa0 = pack2(xp.x, xp.x), xb0 = pack2(xp.y, xp.y);
            const ull xa1 = pack2(xp.z, xp.z), xb1 = pack2(xp.w, xp.w);

            ull acc0 = pack2(s_c[i0], 0.f);   // c[id] folded into acc init
            ull acc1 = pack2(s_c[i1], 0.f);

#pragma unroll
            for (int q = 0; q < 8; q++) {
                const uint2 u0 = v0[q];
                const uint2 u1 = v1[q];
                ull t;
                t = fma2(xa0, rA[2 * q + 0], fma2(xb0, rB[2 * q + 0], rC[2 * q + 0]));
                acc0 = fma2(relu2(t), h2_to_f2(u0.x), acc0);
                t = fma2(xa0, rA[2 * q + 1], fma2(xb0, rB[2 * q + 1], rC[2 * q + 1]));
                acc0 = fma2(relu2(t), h2_to_f2(u0.y), acc0);
                t = fma2(xa1, rA[2 * q + 0], fma2(xb1, rB[2 * q + 0], rC[2 * q + 0]));
                acc1 = fma2(relu2(t), h2_to_f2(u1.x), acc1);
                t = fma2(xa1, rA[2 * q + 1], fma2(xb1, rB[2 * q + 1], rC[2 * q + 1]));
                acc1 = fma2(relu2(t), h2_to_f2(u1.y), acc1);
            }
            out2[p] = make_float2(hsum2(acc0), hsum2(acc1));

            p = pn;
            ids = ids_n;
            xp  = xp_n;
        }
    }

    // Odd-B tail: one scalar row handled by a single thread.
    if ((B & 1) && tid == 0) {
        const int r = B - 1;
        const unsigned id = min((unsigned)bk_s[r], NB - 1u);
        const uint2* v = s_vh + id * 9;
        const ull xa = pack2(x_s[2 * r], x_s[2 * r]);
        const ull xb = pack2(x_s[2 * r + 1], x_s[2 * r + 1]);
        ull acc = pack2(s_c[id], 0.f);
#pragma unroll
        for (int q = 0; q < 8; q++) {
            const uint2 u = v[q];
            ull t;
            t = fma2(xa, rA[2 * q + 0], fma2(xb, rB[2 * q + 0], rC[2 * q + 0]));
            acc = fma2(relu2(t), h2_to_f2(u.x), acc);
            t = fma2(xa, rA[2 * q + 1], fma2(xb, rB[2 * q + 1], rC[2 * q + 1]));
            acc = fma2(relu2(t), h2_to_f2(u.y), acc);
        }
        out_s[r] = hsum2(acc);
    }
}

// ---------------------------------------------------------------------------
// Inputs (metadata order): x[B,2] f32, buckets[B] i32, W1[2,32], b1[32],
//                          W2[32,16], b2[16], Wh[50,16], bh[50]
// Output: float[B]
// ---------------------------------------------------------------------------
extern "C" void kernel_launch(void* const* d_in, const int* in_sizes, int n_in,
                              void* d_out, int out_size) {
    const float* x  = (const float*)d_in[0];
    const int*   bk = (const int*)d_in[1];
    const float* W1 = (const float*)d_in[2];
    const float* b1 = (const float*)d_in[3];
    const float* W2 = (const float*)d_in[4];
    const float* b2 = (const float*)d_in[5];
    const float* Wh = (const float*)d_in[6];
    const float* bh = (const float*)d_in[7];
    float* out = (float*)d_out;

    const int B = in_sizes[1];
    const int npairs = B >> 1;

    lw_precompute<<<14, 128>>>(W1, b1, W2, b2, Wh, bh);
    lw_main<<<GRID, BLOCK>>>((const float4*)x, (const int2*)bk, (float2*)out,
                             npairs, x, bk, out, B);
}